// round 6
// baseline (speedup 1.0000x reference)
#include <cuda_runtime.h>
#include <cstdint>

// Elman RNN: h_t = tanh(X_t @ Ww^T + h_{t-1} @ Uw^T + (Wb+Ub+b))
// T=512, B=64, D_IN=1024, D_OUT=2048. Output: [T*B, D_OUT] fp32.
//
//   1) gemm_xw: Z = X @ Ww^T + bias, in place into d_out.
//   2) tanh0:   h_0 = tanh(Z_0).
//   3) rnn_persistent: ONE kernel, 128 CTAs (16 j-tiles x 8 k-chunks, single
//      wave), loops t=1..511. Sync via scoped atomics (red.release.gpu +
//      ld.acquire.gpu) -- NO gpu-scope fences, so NO CCTL.IVALL L1 flushes.
//      All cross-CTA data (H, Z, partials) moves via __ldcg (L2-only); U is
//      the sole L1 occupant (131KB/CTA) and stays resident across all steps.

#define T_STEPS 512
#define BATCH   64
#define DIN     1024
#define DOUT    2048
#define KSPLIT  8
#define KCHUNK  (DOUT / KSPLIT)   // 256
#define NJT     (DOUT / 128)      // 16 j-tile groups

typedef unsigned long long ull;

__device__ float g_partial[KSPLIT * BATCH * DOUT];   // 4 MB static scratch
__device__ int   g_ctr [T_STEPS][NJT];               // partial-ready counters
__device__ int   g_done[T_STEPS][NJT];               // reduce-done epochs

// ---- f32x2 packed helpers (sm_103a FFMA2 path) ------------------------------
__device__ __forceinline__ ull pk2(float x, float y) {
    ull r;
    asm("mov.b64 %0, {%1, %2};" : "=l"(r)
        : "r"(__float_as_uint(x)), "r"(__float_as_uint(y)));
    return r;
}
__device__ __forceinline__ void upk2(ull v, float& x, float& y) {
    unsigned lo, hi;
    asm("mov.b64 {%0, %1}, %2;" : "=r"(lo), "=r"(hi) : "l"(v));
    x = __uint_as_float(lo); y = __uint_as_float(hi);
}
__device__ __forceinline__ void ffma2(ull& d, ull a, ull b) {
    asm("fma.rn.f32x2 %0, %1, %2, %0;" : "+l"(d) : "l"(a), "l"(b));
}

// ---- scoped-atomic sync primitives (no CCTL.IVALL) --------------------------
__device__ __forceinline__ int ld_acq(const int* p) {
    int v;
    asm volatile("ld.acquire.gpu.global.b32 %0, [%1];" : "=r"(v) : "l"(p) : "memory");
    return v;
}
__device__ __forceinline__ void red_rel_add(int* p) {
    asm volatile("red.release.gpu.global.add.s32 [%0], 1;" :: "l"(p) : "memory");
}
__device__ __forceinline__ void spin_ge(const int* p, int target) {
    while (ld_acq(p) < target) __nanosleep(40);
}

// ---- Kernel 0: zero counters (replay-safe reset) ----------------------------
__global__ void zero_ctr_kernel()
{
    int i = blockIdx.x * blockDim.x + threadIdx.x;
    if (i < T_STEPS * NJT) { ((int*)g_ctr)[i] = 0; ((int*)g_done)[i] = 0; }
}

// ---- Kernel 1: Z = X @ Ww^T + bias  (NT gemm) -------------------------------
// grid: (DOUT/128, TB/128), block 256. Tile 128x128, BK=16, 8x8 per thread.
__global__ __launch_bounds__(256, 2)
void gemm_xw_kernel(const float* __restrict__ X, const float* __restrict__ Ww,
                    const float* __restrict__ Wb, const float* __restrict__ Ubv,
                    const float* __restrict__ bv, float* __restrict__ Z)
{
    __shared__ float As[16][128 + 4];
    __shared__ float Bs[16][128 + 4];
    const int tid = threadIdx.x;
    const int jt  = tid & 15;
    const int it  = tid >> 4;
    const int kq  = tid & 3;
    const int r   = tid >> 2;
    const long rowBase = (long)blockIdx.y * 128;
    const int  colBase = blockIdx.x * 128;

    ull acc[8][4];
    #pragma unroll
    for (int i = 0; i < 8; i++)
        #pragma unroll
        for (int j = 0; j < 4; j++) acc[i][j] = 0ULL;

    for (int k0 = 0; k0 < DIN; k0 += 16) {
        const float* Xp = X + (rowBase + r) * DIN + k0 + kq * 4;
        float4 a0 = *(const float4*)Xp;
        float4 a1 = *(const float4*)(Xp + 64L * DIN);
        As[kq*4+0][r]    = a0.x; As[kq*4+1][r]    = a0.y;
        As[kq*4+2][r]    = a0.z; As[kq*4+3][r]    = a0.w;
        As[kq*4+0][r+64] = a1.x; As[kq*4+1][r+64] = a1.y;
        As[kq*4+2][r+64] = a1.z; As[kq*4+3][r+64] = a1.w;

        const float* Wp = Ww + (long)(colBase + r) * DIN + k0 + kq * 4;
        float4 b0 = *(const float4*)Wp;
        float4 b1 = *(const float4*)(Wp + 64L * DIN);
        Bs[kq*4+0][r]    = b0.x; Bs[kq*4+1][r]    = b0.y;
        Bs[kq*4+2][r]    = b0.z; Bs[kq*4+3][r]    = b0.w;
        Bs[kq*4+0][r+64] = b1.x; Bs[kq*4+1][r+64] = b1.y;
        Bs[kq*4+2][r+64] = b1.z; Bs[kq*4+3][r+64] = b1.w;
        __syncthreads();

        #pragma unroll
        for (int k = 0; k < 16; k++) {
            float4 av0 = *(const float4*)&As[k][it*8];
            float4 av1 = *(const float4*)&As[k][it*8+4];
            float4 bq0 = *(const float4*)&Bs[k][jt*8];
            float4 bq1 = *(const float4*)&Bs[k][jt*8+4];
            ull bp[4] = { pk2(bq0.x,bq0.y), pk2(bq0.z,bq0.w),
                          pk2(bq1.x,bq1.y), pk2(bq1.z,bq1.w) };
            float a_[8] = {av0.x,av0.y,av0.z,av0.w,av1.x,av1.y,av1.z,av1.w};
            #pragma unroll
            for (int ii = 0; ii < 8; ii++) {
                ull asp = pk2(a_[ii], a_[ii]);
                #pragma unroll
                for (int jj = 0; jj < 4; jj++) ffma2(acc[ii][jj], asp, bp[jj]);
            }
        }
        __syncthreads();
    }

    float bias[8];
    #pragma unroll
    for (int jj = 0; jj < 8; jj++) {
        int j = colBase + jt*8 + jj;
        bias[jj] = Wb[j] + Ubv[j] + bv[j];
    }
    #pragma unroll
    for (int ii = 0; ii < 8; ii++) {
        long row = rowBase + it*8 + ii;
        float* op = Z + row * DOUT + colBase + jt*8;
        #pragma unroll
        for (int jj = 0; jj < 4; jj++) {
            float x, y; upk2(acc[ii][jj], x, y);
            *(float2*)(op + jj*2) = make_float2(x + bias[jj*2], y + bias[jj*2+1]);
        }
    }
}

// ---- Kernel 2: h_0 = tanh(Z_0) ----------------------------------------------
__global__ void tanh_kernel(float* __restrict__ zt)
{
    int i4 = blockIdx.x * blockDim.x + threadIdx.x;
    float4 v = ((const float4*)zt)[i4];
    v.x = tanhf(v.x); v.y = tanhf(v.y); v.z = tanhf(v.z); v.w = tanhf(v.w);
    ((float4*)zt)[i4] = v;
}

// ---- Kernel 3: persistent recurrence, t = 1..511 ----------------------------
// grid: (NJT, KSPLIT) = 128 CTAs (single wave), block 128.
// CTA (jx, s): GEMM tile [64b x 128j] over k-chunk s; 8x8/thread FFMA2.
__global__ __launch_bounds__(128, 1)
void rnn_persistent_kernel(float* __restrict__ out, const float* __restrict__ U)
{
    __shared__ float Hs[2][16][64 + 4];
    __shared__ float Us[2][16][128 + 4];
    const int tid = threadIdx.x;
    const int jt  = tid & 15;    // 8 j each
    const int it  = tid >> 4;    // 8 b each (0..7)
    const int rh  = tid >> 1;    // 0..63  H row for loads
    const int kh  = tid & 1;     // H k-quad pair selector
    const int jx  = blockIdx.x;  // j-tile group 0..15
    const int s   = blockIdx.y;  // k-chunk 0..7
    const int jbase = jx * 128;
    const int kbase = s * KCHUNK;
    const int NIT = KCHUNK / 16;   // 16

    const float* Urow = U + (long)(jbase + tid) * DOUT + kbase;
    float* P = g_partial + (long)s * (BATCH * DOUT);

    for (int t = 1; t < T_STEPS; ++t) {
        // ---- wait: h_{t-1} cols for my k-chunk ready (groups 2s, 2s+1), and
        //      my own group's readers done with my partial region (group jx).
        if (t >= 2) {
            if (tid == 0) {
                spin_ge(&g_done[t-1][2*s],   KSPLIT);
                spin_ge(&g_done[t-1][2*s+1], KSPLIT);
                spin_ge(&g_done[t-1][jx],    KSPLIT);
            }
            __syncthreads();
        }

        const float* Hrow = out + (long)(t-1) * BATCH * DOUT
                          + (long)rh * DOUT + kbase;
        float* Zt = out + (long)t * BATCH * DOUT;

        ull acc[8][4];
        #pragma unroll
        for (int i = 0; i < 8; i++)
            #pragma unroll
            for (int j = 0; j < 4; j++) acc[i][j] = 0ULL;

        float4 h0, h1, u0, u1, u2, u3;

        // H via __ldcg (L2-only: fresh cross-CTA data, keeps L1 free for U).
        // U via plain ld (L1-resident after step 1).
#define LDG_ITER(K0) do {                                  \
        h0 = __ldcg((const float4*)(Hrow + (K0) + kh * 4));        \
        h1 = __ldcg((const float4*)(Hrow + (K0) + (kh + 2) * 4));  \
        u0 = *(const float4*)(Urow + (K0));                \
        u1 = *(const float4*)(Urow + (K0) + 4);            \
        u2 = *(const float4*)(Urow + (K0) + 8);            \
        u3 = *(const float4*)(Urow + (K0) + 12);           \
    } while (0)

#define STS_ITER(BUF) do {                                                   \
        Hs[BUF][kh*4+0][rh]  = h0.x; Hs[BUF][kh*4+1][rh]  = h0.y;            \
        Hs[BUF][kh*4+2][rh]  = h0.z; Hs[BUF][kh*4+3][rh]  = h0.w;            \
        Hs[BUF][kh*4+8][rh]  = h1.x; Hs[BUF][kh*4+9][rh]  = h1.y;            \
        Hs[BUF][kh*4+10][rh] = h1.z; Hs[BUF][kh*4+11][rh] = h1.w;            \
        Us[BUF][0][tid]  = u0.x; Us[BUF][1][tid]  = u0.y;                    \
        Us[BUF][2][tid]  = u0.z; Us[BUF][3][tid]  = u0.w;                    \
        Us[BUF][4][tid]  = u1.x; Us[BUF][5][tid]  = u1.y;                    \
        Us[BUF][6][tid]  = u1.z; Us[BUF][7][tid]  = u1.w;                    \
        Us[BUF][8][tid]  = u2.x; Us[BUF][9][tid]  = u2.y;                    \
        Us[BUF][10][tid] = u2.z; Us[BUF][11][tid] = u2.w;                    \
        Us[BUF][12][tid] = u3.x; Us[BUF][13][tid] = u3.y;                    \
        Us[BUF][14][tid] = u3.z; Us[BUF][15][tid] = u3.w;                    \
    } while (0)

        LDG_ITER(0);
        STS_ITER(0);

        for (int itn = 0; itn < NIT; ++itn) {
            __syncthreads();
            if (itn + 1 < NIT) LDG_ITER((itn + 1) * 16);
            const int cur = itn & 1;

            #pragma unroll
            for (int k = 0; k < 16; k++) {
                float4 hv0 = *(const float4*)&Hs[cur][k][it*8];
                float4 hv1 = *(const float4*)&Hs[cur][k][it*8+4];
                float4 uv0 = *(const float4*)&Us[cur][k][jt*8];
                float4 uv1 = *(const float4*)&Us[cur][k][jt*8+4];
                ull up[4] = { pk2(uv0.x,uv0.y), pk2(uv0.z,uv0.w),
                              pk2(uv1.x,uv1.y), pk2(uv1.z,uv1.w) };
                float hb[8] = {hv0.x,hv0.y,hv0.z,hv0.w,hv1.x,hv1.y,hv1.z,hv1.w};
                #pragma unroll
                for (int bi = 0; bi < 8; bi++) {
                    ull hs = pk2(hb[bi], hb[bi]);
                    #pragma unroll
                    for (int jj = 0; jj < 4; jj++) ffma2(acc[bi][jj], hs, up[jj]);
                }
            }

            if (itn + 1 < NIT) STS_ITER((itn + 1) & 1);
        }
#undef LDG_ITER
#undef STS_ITER

        // ---- write partial (STG -> L2; no L1 allocation on store) -----------
        #pragma unroll
        for (int bi = 0; bi < 8; bi++) {
            float* op = P + (long)(it*8 + bi) * DOUT + jbase + jt*8;
            #pragma unroll
            for (int jj = 0; jj < 4; jj++) {
                float x, y; upk2(acc[bi][jj], x, y);
                *(float2*)(op + jj*2) = make_float2(x, y);
            }
        }

        // ---- group barrier: all 8 partials of group jx ready ----------------
        // release: syncthreads (cumulative CTA fence) + tid0 red.release.gpu
        __syncthreads();
        if (tid == 0) {
            red_rel_add(&g_ctr[t][jx]);
            spin_ge(&g_ctr[t][jx], KSPLIT);
        }
        __syncthreads();

        // ---- reduce disjoint 8-row slice (rows s*8..s*8+7) + tanh -----------
        // All reads via __ldcg (L2): partials from peer CTAs bypass stale L1.
        {
            const int rowBase = s * 8;
            #pragma unroll
            for (int e = 0; e < 2; e++) {
                int idx  = (tid * 2 + e) * 4;
                int brow = rowBase + (idx >> 7);
                int col  = jbase + (idx & 127);
                float* zp = Zt + (long)brow * DOUT + col;
                float4 v = __ldcg((const float4*)zp);
                #pragma unroll
                for (int ss = 0; ss < KSPLIT; ss++) {
                    const float4 p = __ldcg((const float4*)(g_partial
                        + (long)ss * (BATCH * DOUT) + (long)brow * DOUT + col));
                    v.x += p.x; v.y += p.y; v.z += p.z; v.w += p.w;
                }
                v.x = tanhf(v.x); v.y = tanhf(v.y);
                v.z = tanhf(v.z); v.w = tanhf(v.w);
                *(float4*)zp = v;
            }
        }

        // ---- signal: my slice of h_t written AND my partial reads done ------
        __syncthreads();
        if (tid == 0) red_rel_add(&g_done[t][jx]);
    }
}

extern "C" void kernel_launch(void* const* d_in, const int* in_sizes, int n_in,
                              void* d_out, int out_size)
{
    const float* X   = (const float*)d_in[0];  // [512,64,1024]
    const float* Ww  = (const float*)d_in[1];  // [2048,1024]
    const float* Wb  = (const float*)d_in[2];  // [2048]
    const float* Uw  = (const float*)d_in[3];  // [2048,2048]
    const float* Ubv = (const float*)d_in[4];  // [2048]
    const float* bv  = (const float*)d_in[5];  // [2048]
    float* out = (float*)d_out;                // [512*64, 2048]

    // Reset counters (replay-safe).
    zero_ctr_kernel<<<(T_STEPS * NJT + 255) / 256, 256>>>();

    // Z for all timesteps, in place in d_out.
    gemm_xw_kernel<<<dim3(DOUT/128, (T_STEPS*BATCH)/128), 256>>>(X, Ww, Wb, Ubv, bv, out);

    // h_0 = tanh(Z_0).
    tanh_kernel<<<(BATCH*DOUT)/(256*4), 256>>>(out);

    // Persistent recurrence: t = 1..511 in one launch.
    rnn_persistent_kernel<<<dim3(NJT, KSPLIT), 128>>>(out, Uw);
}